// round 7
// baseline (speedup 1.0000x reference)
#include <cuda_runtime.h>
#include <cstddef>

// GATNE-T fused, warp-per-2-batch-elements, zero CTA barriers (R7).
// Inputs (metadata order):
//  0 targets   int32  [B]
//  1 types     int32  [B]
//  2 neighbors int32  [B,T,S]
//  3 base_node_embeddings float [V,E]
//  4 node_type_embeddings float [V,T,D]
//  5 trans_weights    float [T,D,E]
//  6 trans_weights_s1 float [T,D,A]
//  7 trans_weights_s2 float [T,A,1]
// Output: float [B,E]

namespace {
constexpr int T = 4;
constexpr int S = 10;
constexpr int D = 32;
constexpr int E = 128;
constexpr int A = 32;
constexpr int NW = 8;          // warps per CTA
constexpr int PB = 2;          // batch elements per warp
}

__device__ __forceinline__ float tanh_approx(float x) {
    float y;
    asm("tanh.approx.f32 %0, %1;" : "=f"(y) : "f"(x));
    return y;
}

// Process one batch element after its gather results are in registers.
// acc[t] holds agg[t][lane] (lane = d). Uses this warp's smem scratch.
__device__ __forceinline__ void finish_b(
    int b, int lane,
    const float* __restrict__ acc,        // [T], lane = d
    float (*sh_agg)[D],                   // [T][D]  per-warp
    float* __restrict__ sh_nat,           // [D]     per-warp
    const float* __restrict__ base_emb,
    const float* __restrict__ tw,
    const float* __restrict__ tw1,
    const float* __restrict__ tw2,
    float* __restrict__ out,
    int ty, int tgt)
{
    #pragma unroll
    for (int t = 0; t < T; ++t) sh_agg[t][lane] = acc[t];

    // attention weights for this b's type (16KB table -> L1 hits)
    float w1col[D];                        // W1[ty][d][lane], lane = a
    {
        const float* w1 = tw1 + (size_t)ty * (D * A);
        #pragma unroll
        for (int d = 0; d < D; ++d) w1col[d] = __ldg(&w1[d * A + lane]);
    }
    const float tw2v = __ldg(&tw2[ty * A + lane]);
    __syncwarp();

    // scores
    float score[T];
    #pragma unroll
    for (int t = 0; t < T; ++t) {
        float dot = 0.0f;
        const float4* ap = (const float4*)sh_agg[t];
        #pragma unroll
        for (int q = 0; q < D / 4; ++q) {
            const float4 v4 = ap[q];       // broadcast LDS.128
            dot = fmaf(v4.x, w1col[4 * q + 0], dot);
            dot = fmaf(v4.y, w1col[4 * q + 1], dot);
            dot = fmaf(v4.z, w1col[4 * q + 2], dot);
            dot = fmaf(v4.w, w1col[4 * q + 3], dot);
        }
        float u = tanh_approx(dot) * tw2v;
        #pragma unroll
        for (int off = 16; off > 0; off >>= 1)
            u += __shfl_xor_sync(0xffffffffu, u, off);
        score[t] = u;
    }

    // softmax over T=4 + attended embedding (lane = d)
    const float m  = fmaxf(fmaxf(score[0], score[1]),
                           fmaxf(score[2], score[3]));
    const float e0 = __expf(score[0] - m), e1 = __expf(score[1] - m);
    const float e2 = __expf(score[2] - m), e3 = __expf(score[3] - m);
    const float inv = 1.0f / (e0 + e1 + e2 + e3);
    sh_nat[lane] = (e0 * acc[0] + e1 * acc[1] +
                    e2 * acc[2] + e3 * acc[3]) * inv;
    __syncwarp();

    // projection: lane owns e in [4*lane, 4*lane+4); 32 LDG.128 L1 hits
    const float* wbase = tw + (size_t)ty * (D * E) + 4 * lane;
    float4 a4 = make_float4(0.f, 0.f, 0.f, 0.f);
    const float4* np = (const float4*)sh_nat;
    #pragma unroll
    for (int q = 0; q < D / 4; ++q) {
        const float4 n4 = np[q];           // broadcast LDS.128
        #pragma unroll
        for (int j = 0; j < 4; ++j) {
            const int d = 4 * q + j;
            const float nd = (j == 0) ? n4.x : (j == 1) ? n4.y
                           : (j == 2) ? n4.z : n4.w;
            const float4 w4 = __ldg((const float4*)(wbase + d * E));
            a4.x = fmaf(nd, w4.x, a4.x);
            a4.y = fmaf(nd, w4.y, a4.y);
            a4.z = fmaf(nd, w4.z, a4.z);
            a4.w = fmaf(nd, w4.w, a4.w);
        }
    }

    const float4 bv = __ldg((const float4*)(base_emb + (size_t)tgt * E) + lane);
    const float4 val = make_float4(a4.x + bv.x, a4.y + bv.y,
                                   a4.z + bv.z, a4.w + bv.w);

    // l2 norm across all 128 outputs (warp butterfly, exact)
    float ss = val.x * val.x + val.y * val.y + val.z * val.z + val.w * val.w;
    #pragma unroll
    for (int off = 16; off > 0; off >>= 1)
        ss += __shfl_xor_sync(0xffffffffu, ss, off);
    const float r = rsqrtf(fmaxf(ss, 1e-12f));

    const float4 o = make_float4(val.x * r, val.y * r, val.z * r, val.w * r);
    ((float4*)(out + (size_t)b * E))[lane] = o;
}

__global__ __launch_bounds__(32 * NW) void gatne_warp2(
    const int*   __restrict__ targets,
    const int*   __restrict__ types,
    const int*   __restrict__ neighbors,  // [B,T,S]
    const float* __restrict__ base_emb,   // [V,E]
    const float* __restrict__ nte,        // [V,T,D]
    const float* __restrict__ tw,         // [T,D,E]
    const float* __restrict__ tw1,        // [T,D,A]
    const float* __restrict__ tw2,        // [T,A]
    float*       __restrict__ out,        // [B,E]
    int B)
{
    const int wid  = threadIdx.x >> 5;
    const int lane = threadIdx.x & 31;

    __shared__ float sh_agg[NW][T][D];
    __shared__ float sh_nat[NW][D];

    const int b0 = (blockIdx.x * NW + wid) * PB;
    if (b0 >= B) return;
    const int b1 = b0 + 1;
    const bool has1 = (b1 < B);

    const int ty0  = types[b0];
    const int tgt0 = targets[b0];
    const int ty1  = has1 ? types[b1]   : 0;
    const int tgt1 = has1 ? targets[b1] : 0;

    // ---- neighbor indices: 4 coalesced loads for 2x40 ints ----
    const int* nbp0 = neighbors + (size_t)b0 * (T * S);
    const int nb00 = nbp0[lane];
    const int nb01 = (lane < T * S - 32) ? nbp0[32 + lane] : 0;
    const int* nbp1 = neighbors + (size_t)b1 * (T * S);
    const int nb10 = has1 ? nbp1[lane] : 0;
    const int nb11 = (has1 && lane < T * S - 32) ? nbp1[32 + lane] : 0;

    // ---- gathers for BOTH b's interleaved: up to 80 independent loads ----
    float acc0[T], acc1[T];
    #pragma unroll
    for (int t = 0; t < T; ++t) { acc0[t] = 0.0f; acc1[t] = 0.0f; }

    #pragma unroll
    for (int t = 0; t < T; ++t) {
        #pragma unroll
        for (int s = 0; s < S; ++s) {
            const int flat = t * S + s;
            const int v0 = (flat < 32)
                ? __shfl_sync(0xffffffffu, nb00, flat)
                : __shfl_sync(0xffffffffu, nb01, flat - 32);
            acc0[t] += __ldg(&nte[(size_t)v0 * (T * D) + t * D + lane]);
            if (has1) {
                const int v1 = (flat < 32)
                    ? __shfl_sync(0xffffffffu, nb10, flat)
                    : __shfl_sync(0xffffffffu, nb11, flat - 32);
                acc1[t] += __ldg(&nte[(size_t)v1 * (T * D) + t * D + lane]);
            }
        }
    }
    #pragma unroll
    for (int t = 0; t < T; ++t) {
        acc0[t] *= (1.0f / (float)S);
        acc1[t] *= (1.0f / (float)S);
    }

    finish_b(b0, lane, acc0, sh_agg[wid], sh_nat[wid],
             base_emb, tw, tw1, tw2, out, ty0, tgt0);
    if (has1) {
        __syncwarp();
        finish_b(b1, lane, acc1, sh_agg[wid], sh_nat[wid],
                 base_emb, tw, tw1, tw2, out, ty1, tgt1);
    }
}

extern "C" void kernel_launch(void* const* d_in, const int* in_sizes, int n_in,
                              void* d_out, int out_size) {
    const int*   targets   = (const int*)  d_in[0];
    const int*   types     = (const int*)  d_in[1];
    const int*   neighbors = (const int*)  d_in[2];
    const float* base_emb  = (const float*)d_in[3];
    const float* nte       = (const float*)d_in[4];
    const float* tw        = (const float*)d_in[5];
    const float* tw1       = (const float*)d_in[6];
    const float* tw2       = (const float*)d_in[7];
    float* out = (float*)d_out;

    const int B = in_sizes[0];
    const int bper = NW * PB;
    const int grid = (B + bper - 1) / bper;
    gatne_warp2<<<grid, 32 * NW>>>(targets, types, neighbors,
                                   base_emb, nte, tw, tw1, tw2, out, B);
}

// round 8
// speedup vs baseline: 1.7789x; 1.7789x over previous
#include <cuda_runtime.h>
#include <cstddef>

// GATNE-T, two-kernel split (R8).
// K1: pure neighbor gather + mean -> g_agg[B,T,D]   (warp-per-b, max MLP)
// K2: attention + projection + l2norm               (warp-per-b, L1-resident)
//
// Inputs (metadata order):
//  0 targets   int32  [B]
//  1 types     int32  [B]
//  2 neighbors int32  [B,T,S]
//  3 base_node_embeddings float [V,E]
//  4 node_type_embeddings float [V,T,D]
//  5 trans_weights    float [T,D,E]
//  6 trans_weights_s1 float [T,D,A]
//  7 trans_weights_s2 float [T,A,1]
// Output: float [B,E]

namespace {
constexpr int T = 4;
constexpr int S = 10;
constexpr int D = 32;
constexpr int E = 128;
constexpr int A = 32;
constexpr int NW = 8;          // warps per CTA (both kernels)
constexpr int MAXB = 8192;
}

__device__ float g_agg[MAXB * T * D];   // mean-aggregated neighbor embeddings

__device__ __forceinline__ float tanh_approx(float x) {
    float y;
    asm("tanh.approx.f32 %0, %1;" : "=f"(y) : "f"(x));
    return y;
}

// ---------------------------------------------------------------------------
// K1: gather only. Warp-per-b. 40 independent coalesced 128B loads per warp,
// issued back-to-back; 4 coalesced 128B stores. No other dependence.
// ---------------------------------------------------------------------------
__global__ __launch_bounds__(32 * NW) void k_gather(
    const int*   __restrict__ neighbors,  // [B,T,S]
    const float* __restrict__ nte,        // [V,T,D]
    int B)
{
    const int wid  = threadIdx.x >> 5;
    const int lane = threadIdx.x & 31;

    const int b = blockIdx.x * NW + wid;
    if (b >= B) return;

    // neighbor indices: 2 coalesced loads for 40 ints, broadcast via shfl
    const int* nbp = neighbors + (size_t)b * (T * S);
    const int nbv0 = nbp[lane];
    const int nbv1 = (lane < T * S - 32) ? nbp[32 + lane] : 0;

    float acc[T];
    #pragma unroll
    for (int t = 0; t < T; ++t) acc[t] = 0.0f;

    #pragma unroll
    for (int t = 0; t < T; ++t) {
        #pragma unroll
        for (int s = 0; s < S; ++s) {
            const int flat = t * S + s;
            const int v = (flat < 32)
                ? __shfl_sync(0xffffffffu, nbv0, flat)
                : __shfl_sync(0xffffffffu, nbv1, flat - 32);
            acc[t] += __ldg(&nte[(size_t)v * (T * D) + t * D + lane]);
        }
    }

    float* ap = g_agg + (size_t)b * (T * D) + lane;
    #pragma unroll
    for (int t = 0; t < T; ++t)
        ap[t * D] = acc[t] * (1.0f / (float)S);   // coalesced 128B stores
}

// ---------------------------------------------------------------------------
// K2: attention + projection + norm. Warp-per-b. All weight tables are
// L1-resident (tw1 16KB, tw2 0.5KB, tw 64KB); agg read is coalesced.
// ---------------------------------------------------------------------------
__global__ __launch_bounds__(32 * NW) void k_compute(
    const int*   __restrict__ targets,
    const int*   __restrict__ types,
    const float* __restrict__ base_emb,   // [V,E]
    const float* __restrict__ tw,         // [T,D,E]
    const float* __restrict__ tw1,        // [T,D,A]
    const float* __restrict__ tw2,        // [T,A]
    float*       __restrict__ out,        // [B,E]
    int B)
{
    const int wid  = threadIdx.x >> 5;
    const int lane = threadIdx.x & 31;

    __shared__ float sh_agg[NW][T][D];
    __shared__ float sh_nat[NW][D];

    const int b = blockIdx.x * NW + wid;
    if (b >= B) return;

    const int ty  = types[b];
    const int tgt = targets[b];

    // agg for this b: 4 coalesced 128B loads (lane = d)
    float acc[T];
    {
        const float* ap = g_agg + (size_t)b * (T * D) + lane;
        #pragma unroll
        for (int t = 0; t < T; ++t) {
            acc[t] = ap[t * D];
            sh_agg[wid][t][lane] = acc[t];
        }
    }

    // attention weights for this b's type (L1 hits)
    float w1col[D];                        // W1[ty][d][lane], lane = a
    {
        const float* w1 = tw1 + (size_t)ty * (D * A);
        #pragma unroll
        for (int d = 0; d < D; ++d) w1col[d] = __ldg(&w1[d * A + lane]);
    }
    const float tw2v = __ldg(&tw2[ty * A + lane]);
    __syncwarp();

    // scores: sc[t] = sum_a w2[a] * tanh( sum_d agg[t,d] * W1[d,a] )
    float score[T];
    #pragma unroll
    for (int t = 0; t < T; ++t) {
        float dot = 0.0f;
        const float4* ap4 = (const float4*)sh_agg[wid][t];
        #pragma unroll
        for (int q = 0; q < D / 4; ++q) {
            const float4 v4 = ap4[q];      // broadcast LDS.128
            dot = fmaf(v4.x, w1col[4 * q + 0], dot);
            dot = fmaf(v4.y, w1col[4 * q + 1], dot);
            dot = fmaf(v4.z, w1col[4 * q + 2], dot);
            dot = fmaf(v4.w, w1col[4 * q + 3], dot);
        }
        float u = tanh_approx(dot) * tw2v;
        #pragma unroll
        for (int off = 16; off > 0; off >>= 1)
            u += __shfl_xor_sync(0xffffffffu, u, off);
        score[t] = u;
    }

    // softmax over T=4 + attended embedding (lane = d)
    const float m  = fmaxf(fmaxf(score[0], score[1]),
                           fmaxf(score[2], score[3]));
    const float e0 = __expf(score[0] - m), e1 = __expf(score[1] - m);
    const float e2 = __expf(score[2] - m), e3 = __expf(score[3] - m);
    const float inv = 1.0f / (e0 + e1 + e2 + e3);
    sh_nat[wid][lane] = (e0 * acc[0] + e1 * acc[1] +
                         e2 * acc[2] + e3 * acc[3]) * inv;
    __syncwarp();

    // projection: lane owns e in [4*lane, 4*lane+4); 32 LDG.128 L1 hits
    const float* wbase = tw + (size_t)ty * (D * E) + 4 * lane;
    float4 a4 = make_float4(0.f, 0.f, 0.f, 0.f);
    const float4* np = (const float4*)sh_nat[wid];
    #pragma unroll
    for (int q = 0; q < D / 4; ++q) {
        const float4 n4 = np[q];           // broadcast LDS.128
        #pragma unroll
        for (int j = 0; j < 4; ++j) {
            const int d = 4 * q + j;
            const float nd = (j == 0) ? n4.x : (j == 1) ? n4.y
                           : (j == 2) ? n4.z : n4.w;
            const float4 w4 = __ldg((const float4*)(wbase + d * E));
            a4.x = fmaf(nd, w4.x, a4.x);
            a4.y = fmaf(nd, w4.y, a4.y);
            a4.z = fmaf(nd, w4.z, a4.z);
            a4.w = fmaf(nd, w4.w, a4.w);
        }
    }

    const float4 bv = __ldg((const float4*)(base_emb + (size_t)tgt * E) + lane);
    const float4 val = make_float4(a4.x + bv.x, a4.y + bv.y,
                                   a4.z + bv.z, a4.w + bv.w);

    // l2 norm across all 128 outputs (warp butterfly, exact)
    float ss = val.x * val.x + val.y * val.y + val.z * val.z + val.w * val.w;
    #pragma unroll
    for (int off = 16; off > 0; off >>= 1)
        ss += __shfl_xor_sync(0xffffffffu, ss, off);
    const float r = rsqrtf(fmaxf(ss, 1e-12f));

    const float4 o = make_float4(val.x * r, val.y * r, val.z * r, val.w * r);
    ((float4*)(out + (size_t)b * E))[lane] = o;
}

extern "C" void kernel_launch(void* const* d_in, const int* in_sizes, int n_in,
                              void* d_out, int out_size) {
    const int*   targets   = (const int*)  d_in[0];
    const int*   types     = (const int*)  d_in[1];
    const int*   neighbors = (const int*)  d_in[2];
    const float* base_emb  = (const float*)d_in[3];
    const float* nte       = (const float*)d_in[4];
    const float* tw        = (const float*)d_in[5];
    const float* tw1       = (const float*)d_in[6];
    const float* tw2       = (const float*)d_in[7];
    float* out = (float*)d_out;

    const int B = in_sizes[0];
    const int grid = (B + NW - 1) / NW;

    k_gather <<<grid, 32 * NW>>>(neighbors, nte, B);
    k_compute<<<grid, 32 * NW>>>(targets, types, base_emb,
                                 tw, tw1, tw2, out, B);
}

// round 9
// speedup vs baseline: 2.5909x; 1.4564x over previous
#include <cuda_runtime.h>
#include <cstddef>

// GATNE-T fused, warp-per-batch-element, zero CTA barriers (R9).
// R6 skeleton + early prefetch of base_emb/attention weights + tanh.approx
// + split projection accumulator chains.
//
// Inputs (metadata order):
//  0 targets   int32  [B]
//  1 types     int32  [B]
//  2 neighbors int32  [B,T,S]
//  3 base_node_embeddings float [V,E]
//  4 node_type_embeddings float [V,T,D]
//  5 trans_weights    float [T,D,E]
//  6 trans_weights_s1 float [T,D,A]
//  7 trans_weights_s2 float [T,A,1]
// Output: float [B,E]

namespace {
constexpr int T = 4;
constexpr int S = 10;
constexpr int D = 32;
constexpr int E = 128;
constexpr int A = 32;
constexpr int NW = 8;          // warps per CTA
}

__device__ __forceinline__ float tanh_approx(float x) {
    float y;
    asm("tanh.approx.f32 %0, %1;" : "=f"(y) : "f"(x));
    return y;
}

__global__ __launch_bounds__(32 * NW) void gatne_warp(
    const int*   __restrict__ targets,
    const int*   __restrict__ types,
    const int*   __restrict__ neighbors,  // [B,T,S]
    const float* __restrict__ base_emb,   // [V,E]
    const float* __restrict__ nte,        // [V,T,D]
    const float* __restrict__ tw,         // [T,D,E]
    const float* __restrict__ tw1,        // [T,D,A]
    const float* __restrict__ tw2,        // [T,A]
    float*       __restrict__ out,        // [B,E]
    int B)
{
    const int wid  = threadIdx.x >> 5;
    const int lane = threadIdx.x & 31;

    // per-warp scratch (no cross-warp sharing, no CTA barriers)
    __shared__ float sh_agg[NW][T][D];
    __shared__ float sh_nat[NW][D];

    const int b = blockIdx.x * NW + wid;
    if (b >= B) return;

    const int ty  = types[b];      // broadcast LDG
    const int tgt = targets[b];    // broadcast LDG

    // ---- PREFETCH the random base_emb gather (256MB table -> DRAM miss).
    // Issued first so its ~600cyc latency overlaps the neighbor gathers.
    const float4 bv = __ldg((const float4*)(base_emb + (size_t)tgt * E) + lane);

    // ---- neighbor indices: 2 coalesced loads for 40 ints ----
    const int* nbp = neighbors + (size_t)b * (T * S);
    const int nbv0 = nbp[lane];
    const int nbv1 = (lane < T * S - 32) ? nbp[32 + lane] : 0;

    // ---- gather + mean: 40 independent coalesced 128B loads, lane = d ----
    float acc[T];
    #pragma unroll
    for (int t = 0; t < T; ++t) acc[t] = 0.0f;

    #pragma unroll
    for (int t = 0; t < T; ++t) {
        #pragma unroll
        for (int s = 0; s < S; ++s) {
            const int flat = t * S + s;
            const int v = (flat < 32)
                ? __shfl_sync(0xffffffffu, nbv0, flat)
                : __shfl_sync(0xffffffffu, nbv1, flat - 32);
            acc[t] += __ldg(&nte[(size_t)v * (T * D) + t * D + lane]);
        }
    }

    // ---- attention weights (L1-resident tables), loaded while gathers fly --
    float w1col[D];                        // W1[ty][d][lane], lane = a
    {
        const float* w1 = tw1 + (size_t)ty * (D * A);
        #pragma unroll
        for (int d = 0; d < D; ++d) w1col[d] = __ldg(&w1[d * A + lane]);
    }
    const float tw2v = __ldg(&tw2[ty * A + lane]);

    #pragma unroll
    for (int t = 0; t < T; ++t) {
        acc[t] *= (1.0f / (float)S);       // agg[t][lane]
        sh_agg[wid][t][lane] = acc[t];
    }
    __syncwarp();

    // ---- scores: u[t][a] = tanh(agg[t] . W1[:,a]);  sc[t] = sum_a u*w2 ----
    float score[T];
    #pragma unroll
    for (int t = 0; t < T; ++t) {
        float d0 = 0.0f, d1 = 0.0f;        // split chains
        const float4* ap = (const float4*)sh_agg[wid][t];
        #pragma unroll
        for (int q = 0; q < D / 4; ++q) {
            const float4 v4 = ap[q];       // broadcast LDS.128
            d0 = fmaf(v4.x, w1col[4 * q + 0], d0);
            d1 = fmaf(v4.y, w1col[4 * q + 1], d1);
            d0 = fmaf(v4.z, w1col[4 * q + 2], d0);
            d1 = fmaf(v4.w, w1col[4 * q + 3], d1);
        }
        float u = tanh_approx(d0 + d1) * tw2v;
        #pragma unroll
        for (int off = 16; off > 0; off >>= 1)
            u += __shfl_xor_sync(0xffffffffu, u, off);
        score[t] = u;
    }

    // ---- softmax over T=4 + attended embedding (lane = d) ----
    const float m  = fmaxf(fmaxf(score[0], score[1]),
                           fmaxf(score[2], score[3]));
    const float e0 = __expf(score[0] - m), e1 = __expf(score[1] - m);
    const float e2 = __expf(score[2] - m), e3 = __expf(score[3] - m);
    const float inv = 1.0f / (e0 + e1 + e2 + e3);
    sh_nat[wid][lane] = (e0 * acc[0] + e1 * acc[1] +
                         e2 * acc[2] + e3 * acc[3]) * inv;
    __syncwarp();

    // ---- projection: lane owns e in [4*lane, 4*lane+4); warp covers E ----
    // 32 LDG.128 L1 hits (tw = 64KB, L1-resident). Two accumulator sets to
    // halve the FMA dependency chain.
    const float* wbase = tw + (size_t)ty * (D * E) + 4 * lane;
    float4 a4 = make_float4(0.f, 0.f, 0.f, 0.f);
    float4 b4 = make_float4(0.f, 0.f, 0.f, 0.f);
    const float4* np = (const float4*)sh_nat[wid];
    #pragma unroll
    for (int q = 0; q < D / 4; ++q) {
        const float4 n4 = np[q];           // broadcast LDS.128
        const float4 w0 = __ldg((const float4*)(wbase + (4 * q + 0) * E));
        const float4 w1 = __ldg((const float4*)(wbase + (4 * q + 1) * E));
        const float4 w2 = __ldg((const float4*)(wbase + (4 * q + 2) * E));
        const float4 w3 = __ldg((const float4*)(wbase + (4 * q + 3) * E));
        a4.x = fmaf(n4.x, w0.x, a4.x); a4.y = fmaf(n4.x, w0.y, a4.y);
        a4.z = fmaf(n4.x, w0.z, a4.z); a4.w = fmaf(n4.x, w0.w, a4.w);
        b4.x = fmaf(n4.y, w1.x, b4.x); b4.y = fmaf(n4.y, w1.y, b4.y);
        b4.z = fmaf(n4.y, w1.z, b4.z); b4.w = fmaf(n4.y, w1.w, b4.w);
        a4.x = fmaf(n4.z, w2.x, a4.x); a4.y = fmaf(n4.z, w2.y, a4.y);
        a4.z = fmaf(n4.z, w2.z, a4.z); a4.w = fmaf(n4.z, w2.w, a4.w);
        b4.x = fmaf(n4.w, w3.x, b4.x); b4.y = fmaf(n4.w, w3.y, b4.y);
        b4.z = fmaf(n4.w, w3.z, b4.z); b4.w = fmaf(n4.w, w3.w, b4.w);
    }

    const float4 val = make_float4(a4.x + b4.x + bv.x, a4.y + b4.y + bv.y,
                                   a4.z + b4.z + bv.z, a4.w + b4.w + bv.w);

    // ---- l2 norm: warp butterfly = exact sum over all 128 outputs ----
    float ss = val.x * val.x + val.y * val.y + val.z * val.z + val.w * val.w;
    #pragma unroll
    for (int off = 16; off > 0; off >>= 1)
        ss += __shfl_xor_sync(0xffffffffu, ss, off);
    const float r = rsqrtf(fmaxf(ss, 1e-12f));

    const float4 o = make_float4(val.x * r, val.y * r, val.z * r, val.w * r);
    ((float4*)(out + (size_t)b * E))[lane] = o;
}

extern "C" void kernel_launch(void* const* d_in, const int* in_sizes, int n_in,
                              void* d_out, int out_size) {
    const int*   targets   = (const int*)  d_in[0];
    const int*   types     = (const int*)  d_in[1];
    const int*   neighbors = (const int*)  d_in[2];
    const float* base_emb  = (const float*)d_in[3];
    const float* nte       = (const float*)d_in[4];
    const float* tw        = (const float*)d_in[5];
    const float* tw1       = (const float*)d_in[6];
    const float* tw2       = (const float*)d_in[7];
    float* out = (float*)d_out;

    const int B = in_sizes[0];
    const int grid = (B + NW - 1) / NW;
    gatne_warp<<<grid, 32 * NW>>>(targets, types, neighbors,
                                  base_emb, nte, tw, tw1, tw2, out, B);
}